// round 11
// baseline (speedup 1.0000x reference)
#include <cuda_runtime.h>
#include <cuda_fp16.h>
#include <cstdint>

#define EMBED 1024
#define HEADS 16
#define HDIM  64
#define NBATCH 2
#define SEQ   2048
#define MTOT  (NBATCH * SEQ)   // 4096

// ---------------- scratch (device globals: allocation-free) ----------------
__device__ __align__(16) __half g_Q[NBATCH * HEADS * SEQ * HDIM];  // [N,H,L,D] prescaled log2e/32
__device__ __align__(16) __half g_K[NBATCH * HEADS * SEQ * HDIM];  // [N,H,L,D]
__device__ __align__(16) __half g_V[NBATCH * HEADS * SEQ * HDIM];  // [N,H,D,L] transposed
__device__ __align__(16) __half g_AO[MTOT * EMBED];                // [N,L,E]
__device__ __align__(16) __half g_xh[MTOT * EMBED];
__device__ __align__(16) __half g_wqh[EMBED * EMBED];
__device__ __align__(16) __half g_wkh[EMBED * EMBED];
__device__ __align__(16) __half g_wvh[EMBED * EMBED];
__device__ __align__(16) __half g_woh[EMBED * EMBED];

// ======================= helpers (arch-neutral PTX) =========================
__device__ __forceinline__ float fexp2(float x) {
    float y;
    asm("ex2.approx.ftz.f32 %0, %1;" : "=f"(y) : "f"(x));
    return y;
}
__device__ __forceinline__ uint32_t smem_u32(const void* p) {
    uint32_t a;
    asm("{ .reg .u64 t; cvta.to.shared.u64 t, %1; cvt.u32.u64 %0, t; }"
        : "=r"(a) : "l"(p));
    return a;
}
__device__ __forceinline__ void cp_async16(uint32_t s, const void* g) {
    asm volatile("cp.async.cg.shared.global [%0], [%1], 16;" :: "r"(s), "l"(g));
}
#define CP_COMMIT() asm volatile("cp.async.commit_group;" ::: "memory")
#define CP_WAIT1()  asm volatile("cp.async.wait_group 1;" ::: "memory")
#define CP_WAIT2()  asm volatile("cp.async.wait_group 2;" ::: "memory")

__device__ __forceinline__ void ldm_x4(uint32_t (&r)[4], uint32_t a) {
    asm volatile("ldmatrix.sync.aligned.m8n8.x4.shared.b16 {%0,%1,%2,%3}, [%4];"
                 : "=r"(r[0]), "=r"(r[1]), "=r"(r[2]), "=r"(r[3]) : "r"(a));
}
__device__ __forceinline__ void ldm_x2(uint32_t (&r)[2], uint32_t a) {
    asm volatile("ldmatrix.sync.aligned.m8n8.x2.shared.b16 {%0,%1}, [%2];"
                 : "=r"(r[0]), "=r"(r[1]) : "r"(a));
}
// fp16 mma m16n8k16, fp32 accumulate
__device__ __forceinline__ void mma_f16(float (&d)[4], const uint32_t (&a)[4],
                                        uint32_t b0, uint32_t b1) {
    asm volatile("mma.sync.aligned.m16n8k16.row.col.f32.f16.f16.f32 "
                 "{%0,%1,%2,%3}, {%4,%5,%6,%7}, {%8,%9}, {%0,%1,%2,%3};"
                 : "+f"(d[0]), "+f"(d[1]), "+f"(d[2]), "+f"(d[3])
                 : "r"(a[0]), "r"(a[1]), "r"(a[2]), "r"(a[3]),
                   "r"(b0), "r"(b1));
}
__device__ __forceinline__ uint32_t h2pack(float a, float b) {
    __half2 h = __floats2half2_rn(a, b);
    return *(uint32_t*)&h;
}
__device__ __forceinline__ uint32_t hexp2(uint32_t d) {
    uint32_t r;
    asm("ex2.approx.f16x2 %0, %1;" : "=r"(r) : "r"(d));
    return r;
}

// ======================= prep: convert fp32 -> fp16 =========================
__global__ void __launch_bounds__(256) prep_cvt(
    const float* __restrict__ x,  const float* __restrict__ wq,
    const float* __restrict__ wk, const float* __restrict__ wv,
    const float* __restrict__ wo)
{
    int t = blockIdx.y;
    const float* src = (t == 0) ? x : (t == 1) ? wq : (t == 2) ? wk
                     : (t == 3) ? wv : wo;
    __half* dst = (t == 0) ? g_xh : (t == 1) ? g_wqh : (t == 2) ? g_wkh
                : (t == 3) ? g_wvh : g_woh;
    int n4 = ((t == 0) ? MTOT * EMBED : EMBED * EMBED) / 4;
    for (int i = blockIdx.x * blockDim.x + threadIdx.x; i < n4;
         i += gridDim.x * blockDim.x) {
        float4 v = ((const float4*)src)[i];
        __half2 h0 = __floats2half2_rn(v.x, v.y);
        __half2 h1 = __floats2half2_rn(v.z, v.w);
        ((uint2*)dst)[i] = make_uint2(*(uint32_t*)&h0, *(uint32_t*)&h1);
    }
}

// ======================= fp16 mma GEMM core (128x128xK) =====================
// BK=32 halfs (64B/row, padded to 80B). 3-stage cp.async, 1 sync/iter.
#define G_RS     80
#define G_TILEB  10240
#define GSTAGE   20480
#define G_SMEM   61440

__device__ __forceinline__ void g_load_tile(const __half* __restrict__ g,
                                            uint32_t s, int k0, int tid) {
#pragma unroll
    for (int t = 0; t < 2; t++) {
        int c = tid + t * 256;
        int row = c >> 2, ch = c & 3;
        cp_async16(s + (uint32_t)(row * G_RS + ch * 16),
                   g + row * EMBED + k0 + ch * 8);
    }
}

__device__ __forceinline__ void gemm_core(const __half* __restrict__ Ag,
                                          const __half* __restrict__ Bg,
                                          uint32_t sbase, int tid,
                                          float acc[4][4][4]) {
    const int w = tid >> 5, l = tid & 31;
    const int wm = (w >> 2) * 64, wn = (w & 3) * 32;
    const uint32_t arow = (uint32_t)(((l >> 3) & 1) * 8 + (l & 7));
    const uint32_t acol = (uint32_t)((l >> 4) * 16);
    const uint32_t brow = (uint32_t)(((l >> 4) & 1) * 8 + (l & 7));
    const uint32_t bcol = (uint32_t)(((l >> 3) & 1) * 16);

    uint32_t sA = sbase, sB = sbase + G_TILEB;
    g_load_tile(Ag, sA, 0, tid);  g_load_tile(Bg, sB, 0, tid);  CP_COMMIT();
    g_load_tile(Ag, sA + GSTAGE, 32, tid);
    g_load_tile(Bg, sB + GSTAGE, 32, tid);  CP_COMMIT();

    for (int i = 0; i < 32; i++) {
        CP_WAIT1();
        __syncthreads();
        if (i + 2 < 32) {
            uint32_t po = (uint32_t)((i + 2) % 3) * GSTAGE;
            g_load_tile(Ag, sA + po, (i + 2) * 32, tid);
            g_load_tile(Bg, sB + po, (i + 2) * 32, tid);
        }
        CP_COMMIT();
        uint32_t bo = (uint32_t)(i % 3) * GSTAGE;
        uint32_t ab = sA + bo, bb = sB + bo;
#pragma unroll
        for (int ks = 0; ks < 2; ks++) {
            uint32_t kk2 = (uint32_t)(ks * 32);
            uint32_t a[4][4];
#pragma unroll
            for (int mt = 0; mt < 4; mt++)
                ldm_x4(a[mt], ab + (wm + mt * 16 + arow) * G_RS + acol + kk2);
#pragma unroll
            for (int bp = 0; bp < 2; bp++) {
                uint32_t b[4];
                ldm_x4(b, bb + (wn + bp * 16 + brow) * G_RS + bcol + kk2);
#pragma unroll
                for (int mt = 0; mt < 4; mt++) {
                    mma_f16(acc[mt][bp * 2 + 0], a[mt], b[0], b[1]);
                    mma_f16(acc[mt][bp * 2 + 1], a[mt], b[2], b[3]);
                }
            }
        }
    }
}

// ---------------------------- QKV -------------------------------------------
__global__ void __launch_bounds__(256, 2) qkv_tc()
{
    extern __shared__ char dyn[];
    uint32_t sbase = smem_u32(dyn);
    const int tid = threadIdx.x, w = tid >> 5, l = tid & 31;
    const int row0 = blockIdx.y * 128, col0 = blockIdx.x * 128;
    const __half* W = (blockIdx.z == 0) ? g_wqh : (blockIdx.z == 1) ? g_wkh : g_wvh;

    float acc[4][4][4] = {};
    gemm_core(g_xh + row0 * EMBED, W + col0 * EMBED, sbase, tid, acc);

    const int wm = (w >> 2) * 64, wn = (w & 3) * 32;
    const int nb = row0 >> 11;
    const float qscale = 1.4426950408889634f / 32.0f;   // log2(e)/sqrt(E)

    if (blockIdx.z < 2) {
        __half* dst = (blockIdx.z == 0) ? g_Q : g_K;
        float sc = (blockIdx.z == 0) ? qscale : 1.0f;
#pragma unroll
        for (int mt = 0; mt < 4; mt++) {
            int r  = row0 + wm + mt * 16 + (l >> 2);
            int ll = r & (SEQ - 1);
#pragma unroll
            for (int nt = 0; nt < 4; nt++) {
                int cc = col0 + wn + nt * 8 + 2 * (l & 3);
                int h = cc >> 6, d = cc & 63;
                __half* p = dst + ((nb * HEADS + h) * SEQ + ll) * HDIM + d;
                __half2 v0 = __floats2half2_rn(acc[mt][nt][0] * sc, acc[mt][nt][1] * sc);
                __half2 v1 = __floats2half2_rn(acc[mt][nt][2] * sc, acc[mt][nt][3] * sc);
                *(__half2*)p = v0;
                *(__half2*)(p + 8 * HDIM) = v1;
            }
        }
    } else {
        // V: transpose via smem -> g_V [N,H,D,L] fp16
        __half* ts = (__half*)dyn;            // [128 cc][136]
        __syncthreads();
#pragma unroll
        for (int mt = 0; mt < 4; mt++) {
            int r = wm + mt * 16 + (l >> 2);
#pragma unroll
            for (int nt = 0; nt < 4; nt++) {
                int cc = wn + nt * 8 + 2 * (l & 3);
                ts[cc * 136 + r]           = __float2half_rn(acc[mt][nt][0]);
                ts[(cc + 1) * 136 + r]     = __float2half_rn(acc[mt][nt][1]);
                ts[cc * 136 + r + 8]       = __float2half_rn(acc[mt][nt][2]);
                ts[(cc + 1) * 136 + r + 8] = __float2half_rn(acc[mt][nt][3]);
            }
        }
        __syncthreads();
        int l0base = row0 & (SEQ - 1);
#pragma unroll
        for (int q = 0; q < 8; q++) {
            int e  = q * 256 + tid;
            int cc = e >> 4;
            int ls = e & 15;
            uint4 v = *(const uint4*)&ts[cc * 136 + ls * 8];
            int gc = col0 + cc;
            int h = gc >> 6, d = gc & 63;
            *(uint4*)(g_V + ((nb * HEADS + h) * HDIM + d) * SEQ + l0base + ls * 8) = v;
        }
    }
}

// ---------------------------- proj ------------------------------------------
__global__ void __launch_bounds__(256, 2) proj_tc(
    const float* __restrict__ bo, float* __restrict__ out)
{
    extern __shared__ char dyn[];
    uint32_t sbase = smem_u32(dyn);
    const int tid = threadIdx.x, w = tid >> 5, l = tid & 31;
    const int row0 = blockIdx.y * 128, col0 = blockIdx.x * 128;

    float acc[4][4][4] = {};
    gemm_core(g_AO + row0 * EMBED, g_woh + col0 * EMBED, sbase, tid, acc);

    const int wm = (w >> 2) * 64, wn = (w & 3) * 32;
#pragma unroll
    for (int mt = 0; mt < 4; mt++) {
        int r = row0 + wm + mt * 16 + (l >> 2);
#pragma unroll
        for (int nt = 0; nt < 4; nt++) {
            int cc = col0 + wn + nt * 8 + 2 * (l & 3);
            float b0 = bo[cc], b1 = bo[cc + 1];
            *(float2*)(out + r * EMBED + cc) =
                make_float2(acc[mt][nt][0] + b0, acc[mt][nt][1] + b1);
            *(float2*)(out + (r + 8) * EMBED + cc) =
                make_float2(acc[mt][nt][2] + b0, acc[mt][nt][3] + b1);
        }
    }
}

// ======================= flash attention, fp16 mma ==========================
// CTA per (qtile128, head, batch). 8 warps, warp = 16 q rows.
// P stays in registers (C-layout == A-layout identity). exp via ex2.f16x2.
// li accumulated BY THE TENSOR CORE: V^T tile carries an all-ones d-row
// (row 64; rows 65-71 zero), so P @ ones accumulates row-sums into a
// dedicated fp32 accumulator that is rescaled exactly like O.
// smem: Q[128][72h], K 3x[64][72h], V^T 3x[72][72h]. 3-stage, 1 sync/iter.
#define A_RS    144                   // bytes per row (72 halfs)
#define A_QP    18432                 // 128 * 144
#define A_KV    9216                  // K stage: 64 * 144
#define A_VST   10368                 // V stage: 72 * 144 (64 kv + ones/zero)
#define A_OFF_K A_QP
#define A_OFF_V (A_QP + 3 * A_KV)
#define A_SMEM  (A_QP + 3 * A_KV + 3 * A_VST)   // 77184

__device__ __forceinline__ void load_kv(const __half* __restrict__ Kg,
                                        const __half* __restrict__ Vg,
                                        uint32_t kbuf, uint32_t vbuf,
                                        int kv0, int tid) {
#pragma unroll
    for (int t = 0; t < 2; t++) {
        int c = tid + t * 256;
        int r = c >> 3, ch = c & 7;
        cp_async16(kbuf + (uint32_t)(r * A_RS + ch * 16),
                   Kg + (kv0 + r) * HDIM + ch * 8);
    }
#pragma unroll
    for (int t = 0; t < 2; t++) {
        int c = tid + t * 256;
        int r = c >> 3, ch = c & 7;   // r = d row of V^T (0..63)
        cp_async16(vbuf + (uint32_t)(r * A_RS + ch * 16),
                   Vg + r * SEQ + kv0 + ch * 8);
    }
}

__global__ void __launch_bounds__(256, 2) attn_tc()
{
    extern __shared__ char dyn[];
    uint32_t sb = smem_u32(dyn);
    const int tid = threadIdx.x, w = tid >> 5, l = tid & 31;
    const int qb = blockIdx.x, h = blockIdx.y, nb = blockIdx.z;

    const __half* Qg = g_Q + ((nb * HEADS + h) * SEQ + qb * 128) * HDIM;
    const __half* Kg = g_K + (nb * HEADS + h) * SEQ * HDIM;
    const __half* Vg = g_V + (nb * HEADS + h) * HDIM * SEQ;   // [D][L]

    uint32_t sQ = sb, sK = sb + A_OFF_K, sV = sb + A_OFF_V;

    // Q tile FIRST (oldest cp.async group)
#pragma unroll
    for (int t = 0; t < 4; t++) {
        int c = tid + t * 256;
        int r = c >> 3, ch = c & 7;
        cp_async16(sQ + (uint32_t)(r * A_RS + ch * 16),
                   Qg + r * HDIM + ch * 8);
    }
    CP_COMMIT();
    load_kv(Kg, Vg, sK, sV, 0, tid);  CP_COMMIT();
    load_kv(Kg, Vg, sK + A_KV, sV + A_VST, 64, tid);  CP_COMMIT();

    // init ones/zero rows (64..71) of all 3 V stages (cp.async never touches them)
    {
        __half* smh = (__half*)dyn;
        for (int idx = tid; idx < 3 * 8 * 72; idx += 256) {
            int st = idx / (8 * 72);
            int rr = (idx / 72) & 7;
            int cc = idx % 72;
            smh[(A_OFF_V + st * A_VST + (64 + rr) * A_RS) / 2 + cc] =
                (rr == 0) ? __float2half_rn(1.0f) : __float2half_rn(0.0f);
        }
    }

    const int wm = w * 16;
    const uint32_t arow = (uint32_t)(((l >> 3) & 1) * 8 + (l & 7));
    const uint32_t acol = (uint32_t)((l >> 4) * 16);
    const uint32_t brow = (uint32_t)(((l >> 4) & 1) * 8 + (l & 7));
    const uint32_t bcol = (uint32_t)(((l >> 3) & 1) * 16);
    const uint32_t orow = (uint32_t)(64 + (l & 7));            // ones rows
    const uint32_t ocol = (uint32_t)(((l >> 3) & 1) * 16);

    // hoist Q fragments (loop-invariant); also publishes ones-rows
    CP_WAIT2();          // Q group retired
    __syncthreads();     // Q + ones visible CTA-wide
    uint32_t qf[4][4];
#pragma unroll
    for (int ks = 0; ks < 4; ks++)
        ldm_x4(qf[ks], sQ + (wm + arow) * A_RS + acol + (uint32_t)(ks * 32));

    float o[8][4] = {};
    float o5[4] = {};                 // li accumulator (col 64 = ones column)
    float mi0 = -1e30f, mi1 = -1e30f;

    const int NIT = SEQ / 64;
    for (int it = 0; it < NIT; it++) {
        CP_WAIT1();
        __syncthreads();
        if (it + 2 < NIT) {
            load_kv(Kg, Vg, sK + (uint32_t)((it + 2) % 3) * A_KV,
                    sV + (uint32_t)((it + 2) % 3) * A_VST, (it + 2) * 64, tid);
        }
        CP_COMMIT();
        uint32_t kb = sK + (uint32_t)(it % 3) * A_KV;
        uint32_t vb = sV + (uint32_t)(it % 3) * A_VST;

        // ---- S = Q @ K^T (Q frags in regs) ----
        float sv[8][4] = {};
#pragma unroll
        for (int ks = 0; ks < 4; ks++) {
            uint32_t kk2 = (uint32_t)(ks * 32);
#pragma unroll
            for (int bp = 0; bp < 4; bp++) {
                uint32_t b[4];
                ldm_x4(b, kb + (bp * 16 + brow) * A_RS + bcol + kk2);
                mma_f16(sv[bp * 2 + 0], qf[ks], b[0], b[1]);
                mma_f16(sv[bp * 2 + 1], qf[ks], b[2], b[3]);
            }
        }

        // ---- row max + rescale ----
        float rm0 = -1e30f, rm1 = -1e30f;
#pragma unroll
        for (int nt = 0; nt < 8; nt++) {
            rm0 = fmaxf(rm0, fmaxf(sv[nt][0], sv[nt][1]));
            rm1 = fmaxf(rm1, fmaxf(sv[nt][2], sv[nt][3]));
        }
#pragma unroll
        for (int off = 1; off <= 2; off <<= 1) {
            rm0 = fmaxf(rm0, __shfl_xor_sync(0xffffffffu, rm0, off));
            rm1 = fmaxf(rm1, __shfl_xor_sync(0xffffffffu, rm1, off));
        }
        float mn0 = fmaxf(mi0, rm0), mn1 = fmaxf(mi1, rm1);
        float c0 = fexp2(mi0 - mn0), c1 = fexp2(mi1 - mn1);
        mi0 = mn0;  mi1 = mn1;
#pragma unroll
        for (int dt = 0; dt < 8; dt++) {
            o[dt][0] *= c0; o[dt][1] *= c0; o[dt][2] *= c1; o[dt][3] *= c1;
        }
        o5[0] *= c0; o5[1] *= c0; o5[2] *= c1; o5[3] *= c1;

        // ---- per k-slice: exp (f16x2) -> P frags -> PV + li mma ----
#pragma unroll
        for (int ks = 0; ks < 4; ks++) {
            uint32_t pa[4];
            pa[0] = hexp2(h2pack(sv[2*ks][0] - mn0,   sv[2*ks][1] - mn0));
            pa[1] = hexp2(h2pack(sv[2*ks][2] - mn1,   sv[2*ks][3] - mn1));
            pa[2] = hexp2(h2pack(sv[2*ks+1][0] - mn0, sv[2*ks+1][1] - mn0));
            pa[3] = hexp2(h2pack(sv[2*ks+1][2] - mn1, sv[2*ks+1][3] - mn1));
            uint32_t kk2 = (uint32_t)(ks * 32);
            // li: P @ ones-column (row 64 of V^T tile)
            uint32_t ob[2];
            ldm_x2(ob, vb + orow * A_RS + ocol + kk2);
            mma_f16(o5, pa, ob[0], ob[1]);
#pragma unroll
            for (int bp = 0; bp < 4; bp++) {
                uint32_t b[4];
                ldm_x4(b, vb + (bp * 16 + brow) * A_RS + bcol + kk2);
                mma_f16(o[bp * 2 + 0], pa, b[0], b[1]);
                mma_f16(o[bp * 2 + 1], pa, b[2], b[3]);
            }
        }
    }

    // li lives in lanes with (l&3)==0: o5[0] = li(row g), o5[2] = li(row g+8)
    float li0 = __shfl_sync(0xffffffffu, o5[0], l & ~3);
    float li1 = __shfl_sync(0xffffffffu, o5[2], l & ~3);

    // epilogue -> g_AO fp16 [N,L,E]
    float inv0 = 1.f / li0, inv1 = 1.f / li1;
    int r0 = qb * 128 + wm + (l >> 2);
    __half* Og = g_AO + (nb * SEQ + r0) * EMBED + h * HDIM;
#pragma unroll
    for (int dt = 0; dt < 8; dt++) {
        int cc = dt * 8 + 2 * (l & 3);
        __half2 v0 = __floats2half2_rn(o[dt][0] * inv0, o[dt][1] * inv0);
        __half2 v1 = __floats2half2_rn(o[dt][2] * inv1, o[dt][3] * inv1);
        *(__half2*)(Og + cc) = v0;
        *(__half2*)(Og + 8 * EMBED + cc) = v1;
    }
}

// ============================================================================
extern "C" void kernel_launch(void* const* d_in, const int* in_sizes, int n_in,
                              void* d_out, int out_size)
{
    const float* x  = (const float*)d_in[0];
    const float* Wq = (const float*)d_in[1];
    const float* Wk = (const float*)d_in[2];
    const float* Wv = (const float*)d_in[3];
    const float* Wo = (const float*)d_in[4];
    const float* bo = (const float*)d_in[5];
    float* out = (float*)d_out;

    cudaFuncSetAttribute(qkv_tc,  cudaFuncAttributeMaxDynamicSharedMemorySize, G_SMEM);
    cudaFuncSetAttribute(proj_tc, cudaFuncAttributeMaxDynamicSharedMemorySize, G_SMEM);
    cudaFuncSetAttribute(attn_tc, cudaFuncAttributeMaxDynamicSharedMemorySize, A_SMEM);
    cudaFuncSetAttribute(qkv_tc,  cudaFuncAttributePreferredSharedMemoryCarveout,
                         cudaSharedmemCarveoutMaxShared);
    cudaFuncSetAttribute(proj_tc, cudaFuncAttributePreferredSharedMemoryCarveout,
                         cudaSharedmemCarveoutMaxShared);
    cudaFuncSetAttribute(attn_tc, cudaFuncAttributePreferredSharedMemoryCarveout,
                         cudaSharedmemCarveoutMaxShared);

    dim3 gp(512, 5);
    prep_cvt<<<gp, 256>>>(x, Wq, Wk, Wv, Wo);

    dim3 g1(EMBED / 128, MTOT / 128, 3);
    qkv_tc<<<g1, 256, G_SMEM>>>();

    dim3 g2(SEQ / 128, HEADS, NBATCH);
    attn_tc<<<g2, 256, A_SMEM>>>();

    dim3 g3(EMBED / 128, MTOT / 128);
    proj_tc<<<g3, 256, G_SMEM>>>(bo, out);
}

// round 13
// speedup vs baseline: 1.0494x; 1.0494x over previous
#include <cuda_runtime.h>
#include <cuda_fp16.h>
#include <cstdint>

#define EMBED 1024
#define HEADS 16
#define HDIM  64
#define NBATCH 2
#define SEQ   2048
#define MTOT  (NBATCH * SEQ)   // 4096

// ---------------- scratch (device globals: allocation-free) ----------------
__device__ __align__(16) __half g_Q[NBATCH * HEADS * SEQ * HDIM];  // [N,H,L,D] prescaled log2e/32
__device__ __align__(16) __half g_K[NBATCH * HEADS * SEQ * HDIM];  // [N,H,L,D]
__device__ __align__(16) __half g_V[NBATCH * HEADS * SEQ * HDIM];  // [N,H,D,L] transposed
__device__ __align__(16) __half g_AO[MTOT * EMBED];                // [N,L,E]
__device__ __align__(16) __half g_xh[MTOT * EMBED];
__device__ __align__(16) __half g_wqh[EMBED * EMBED];
__device__ __align__(16) __half g_wkh[EMBED * EMBED];
__device__ __align__(16) __half g_wvh[EMBED * EMBED];
__device__ __align__(16) __half g_woh[EMBED * EMBED];

// ======================= helpers (arch-neutral PTX) =========================
__device__ __forceinline__ float fexp2(float x) {
    float y;
    asm("ex2.approx.ftz.f32 %0, %1;" : "=f"(y) : "f"(x));
    return y;
}
__device__ __forceinline__ uint32_t smem_u32(const void* p) {
    uint32_t a;
    asm("{ .reg .u64 t; cvta.to.shared.u64 t, %1; cvt.u32.u64 %0, t; }"
        : "=r"(a) : "l"(p));
    return a;
}
__device__ __forceinline__ void cp_async16(uint32_t s, const void* g) {
    asm volatile("cp.async.cg.shared.global [%0], [%1], 16;" :: "r"(s), "l"(g));
}
#define CP_COMMIT() asm volatile("cp.async.commit_group;" ::: "memory")
#define CP_WAIT1()  asm volatile("cp.async.wait_group 1;" ::: "memory")
#define CP_WAIT2()  asm volatile("cp.async.wait_group 2;" ::: "memory")

__device__ __forceinline__ void ldm_x4(uint32_t (&r)[4], uint32_t a) {
    asm volatile("ldmatrix.sync.aligned.m8n8.x4.shared.b16 {%0,%1,%2,%3}, [%4];"
                 : "=r"(r[0]), "=r"(r[1]), "=r"(r[2]), "=r"(r[3]) : "r"(a));
}
__device__ __forceinline__ void ldm_x2(uint32_t (&r)[2], uint32_t a) {
    asm volatile("ldmatrix.sync.aligned.m8n8.x2.shared.b16 {%0,%1}, [%2];"
                 : "=r"(r[0]), "=r"(r[1]) : "r"(a));
}
// fp16 mma m16n8k16, fp32 accumulate
__device__ __forceinline__ void mma_f16(float (&d)[4], const uint32_t (&a)[4],
                                        uint32_t b0, uint32_t b1) {
    asm volatile("mma.sync.aligned.m16n8k16.row.col.f32.f16.f16.f32 "
                 "{%0,%1,%2,%3}, {%4,%5,%6,%7}, {%8,%9}, {%0,%1,%2,%3};"
                 : "+f"(d[0]), "+f"(d[1]), "+f"(d[2]), "+f"(d[3])
                 : "r"(a[0]), "r"(a[1]), "r"(a[2]), "r"(a[3]),
                   "r"(b0), "r"(b1));
}
// fp16 mma m16n8k16, fp16 accumulate (d0 = row g cols 2t/2t+1, d1 = row g+8)
__device__ __forceinline__ void mma_f16h(uint32_t& d0, uint32_t& d1,
                                         const uint32_t (&a)[4],
                                         uint32_t b0, uint32_t b1) {
    asm volatile("mma.sync.aligned.m16n8k16.row.col.f16.f16.f16.f16 "
                 "{%0,%1}, {%2,%3,%4,%5}, {%6,%7}, {%0,%1};"
                 : "+r"(d0), "+r"(d1)
                 : "r"(a[0]), "r"(a[1]), "r"(a[2]), "r"(a[3]),
                   "r"(b0), "r"(b1));
}
__device__ __forceinline__ uint32_t hexp2(uint32_t d) {
    uint32_t r;
    asm("ex2.approx.f16x2 %0, %1;" : "=r"(r) : "r"(d));
    return r;
}
__device__ __forceinline__ uint32_t hmax2u(uint32_t a, uint32_t b) {
    __half2 r = __hmax2(*(__half2*)&a, *(__half2*)&b);
    return *(uint32_t*)&r;
}
__device__ __forceinline__ uint32_t hsub2u(uint32_t a, uint32_t b) {
    __half2 r = __hsub2(*(__half2*)&a, *(__half2*)&b);
    return *(uint32_t*)&r;
}
__device__ __forceinline__ float h2max_f(uint32_t a) {
    __half2 h = *(__half2*)&a;
    return fmaxf(__half2float(__low2half(h)), __half2float(__high2half(h)));
}

// ======================= prep: convert fp32 -> fp16 =========================
__global__ void __launch_bounds__(256) prep_cvt(
    const float* __restrict__ x,  const float* __restrict__ wq,
    const float* __restrict__ wk, const float* __restrict__ wv,
    const float* __restrict__ wo)
{
    int t = blockIdx.y;
    const float* src = (t == 0) ? x : (t == 1) ? wq : (t == 2) ? wk
                     : (t == 3) ? wv : wo;
    __half* dst = (t == 0) ? g_xh : (t == 1) ? g_wqh : (t == 2) ? g_wkh
                : (t == 3) ? g_wvh : g_woh;
    int n4 = ((t == 0) ? MTOT * EMBED : EMBED * EMBED) / 4;
    for (int i = blockIdx.x * blockDim.x + threadIdx.x; i < n4;
         i += gridDim.x * blockDim.x) {
        float4 v = ((const float4*)src)[i];
        __half2 h0 = __floats2half2_rn(v.x, v.y);
        __half2 h1 = __floats2half2_rn(v.z, v.w);
        ((uint2*)dst)[i] = make_uint2(*(uint32_t*)&h0, *(uint32_t*)&h1);
    }
}

// ======================= fp16 mma GEMM core (128x128xK) =====================
// BK=64 halfs (128B/row, padded to 144B). 3-stage cp.async, 1 sync per BK=64.
#define G_RS     144                  // row stride bytes (72 halfs)
#define G_TILEB  18432                // 128 * 144
#define GSTAGE   36864                // A + B
#define G_SMEM   110592               // 3 stages

__device__ __forceinline__ void g_load_tile(const __half* __restrict__ g,
                                            uint32_t s, int k0, int tid) {
#pragma unroll
    for (int t = 0; t < 4; t++) {
        int c = tid + t * 256;        // 0..1023 16B chunks
        int row = c >> 3, ch = c & 7;
        cp_async16(s + (uint32_t)(row * G_RS + ch * 16),
                   g + row * EMBED + k0 + ch * 8);
    }
}

__device__ __forceinline__ void gemm_core(const __half* __restrict__ Ag,
                                          const __half* __restrict__ Bg,
                                          uint32_t sbase, int tid,
                                          float acc[4][4][4]) {
    const int w = tid >> 5, l = tid & 31;
    const int wm = (w >> 2) * 64, wn = (w & 3) * 32;
    const uint32_t arow = (uint32_t)(l & 15);
    const uint32_t acol = (uint32_t)((l >> 4) * 16);
    const uint32_t brow = (uint32_t)(((l >> 4) & 1) * 8 + (l & 7));
    const uint32_t bcol = (uint32_t)(((l >> 3) & 1) * 16);

    uint32_t sA = sbase, sB = sbase + G_TILEB;
    g_load_tile(Ag, sA, 0, tid);  g_load_tile(Bg, sB, 0, tid);  CP_COMMIT();
    g_load_tile(Ag, sA + GSTAGE, 64, tid);
    g_load_tile(Bg, sB + GSTAGE, 64, tid);  CP_COMMIT();

    const int NIT = EMBED / 64;       // 16
    for (int i = 0; i < NIT; i++) {
        CP_WAIT1();
        __syncthreads();
        if (i + 2 < NIT) {
            uint32_t po = (uint32_t)((i + 2) % 3) * GSTAGE;
            g_load_tile(Ag, sA + po, (i + 2) * 64, tid);
            g_load_tile(Bg, sB + po, (i + 2) * 64, tid);
        }
        CP_COMMIT();
        uint32_t bo = (uint32_t)(i % 3) * GSTAGE;
        uint32_t ab = sA + bo, bb = sB + bo;
#pragma unroll
        for (int ks = 0; ks < 4; ks++) {       // four k16 slices per BK=64
            uint32_t kk2 = (uint32_t)(ks * 32);
            uint32_t a[4][4];
#pragma unroll
            for (int mt = 0; mt < 4; mt++)
                ldm_x4(a[mt], ab + (wm + mt * 16 + arow) * G_RS + acol + kk2);
#pragma unroll
            for (int bp = 0; bp < 2; bp++) {
                uint32_t b[4];
                ldm_x4(b, bb + (wn + bp * 16 + brow) * G_RS + bcol + kk2);
#pragma unroll
                for (int mt = 0; mt < 4; mt++) {
                    mma_f16(acc[mt][bp * 2 + 0], a[mt], b[0], b[1]);
                    mma_f16(acc[mt][bp * 2 + 1], a[mt], b[2], b[3]);
                }
            }
        }
    }
}

// ---------------------------- QKV -------------------------------------------
__global__ void __launch_bounds__(256, 2) qkv_tc()
{
    extern __shared__ char dyn[];
    uint32_t sbase = smem_u32(dyn);
    const int tid = threadIdx.x, w = tid >> 5, l = tid & 31;
    const int row0 = blockIdx.y * 128, col0 = blockIdx.x * 128;
    const __half* W = (blockIdx.z == 0) ? g_wqh : (blockIdx.z == 1) ? g_wkh : g_wvh;

    float acc[4][4][4] = {};
    gemm_core(g_xh + row0 * EMBED, W + col0 * EMBED, sbase, tid, acc);

    const int wm = (w >> 2) * 64, wn = (w & 3) * 32;
    const int nb = row0 >> 11;
    const float qscale = 1.4426950408889634f / 32.0f;   // log2(e)/sqrt(E)

    if (blockIdx.z < 2) {
        __half* dst = (blockIdx.z == 0) ? g_Q : g_K;
        float sc = (blockIdx.z == 0) ? qscale : 1.0f;
#pragma unroll
        for (int mt = 0; mt < 4; mt++) {
            int r  = row0 + wm + mt * 16 + (l >> 2);
            int ll = r & (SEQ - 1);
#pragma unroll
            for (int nt = 0; nt < 4; nt++) {
                int cc = col0 + wn + nt * 8 + 2 * (l & 3);
                int h = cc >> 6, d = cc & 63;
                __half* p = dst + ((nb * HEADS + h) * SEQ + ll) * HDIM + d;
                __half2 v0 = __floats2half2_rn(acc[mt][nt][0] * sc, acc[mt][nt][1] * sc);
                __half2 v1 = __floats2half2_rn(acc[mt][nt][2] * sc, acc[mt][nt][3] * sc);
                *(__half2*)p = v0;
                *(__half2*)(p + 8 * HDIM) = v1;
            }
        }
    } else {
        // V: transpose via smem -> g_V [N,H,D,L] fp16
        __half* ts = (__half*)dyn;            // [128 cc][136]
        __syncthreads();
#pragma unroll
        for (int mt = 0; mt < 4; mt++) {
            int r = wm + mt * 16 + (l >> 2);
#pragma unroll
            for (int nt = 0; nt < 4; nt++) {
                int cc = wn + nt * 8 + 2 * (l & 3);
                ts[cc * 136 + r]           = __float2half_rn(acc[mt][nt][0]);
                ts[(cc + 1) * 136 + r]     = __float2half_rn(acc[mt][nt][1]);
                ts[cc * 136 + r + 8]       = __float2half_rn(acc[mt][nt][2]);
                ts[(cc + 1) * 136 + r + 8] = __float2half_rn(acc[mt][nt][3]);
            }
        }
        __syncthreads();
        int l0base = row0 & (SEQ - 1);
#pragma unroll
        for (int q = 0; q < 8; q++) {
            int e  = q * 256 + tid;
            int cc = e >> 4;
            int ls = e & 15;
            uint4 v = *(const uint4*)&ts[cc * 136 + ls * 8];
            int gc = col0 + cc;
            int h = gc >> 6, d = gc & 63;
            *(uint4*)(g_V + ((nb * HEADS + h) * HDIM + d) * SEQ + l0base + ls * 8) = v;
        }
    }
}

// ---------------------------- proj ------------------------------------------
__global__ void __launch_bounds__(256, 2) proj_tc(
    const float* __restrict__ bo, float* __restrict__ out)
{
    extern __shared__ char dyn[];
    uint32_t sbase = smem_u32(dyn);
    const int tid = threadIdx.x, w = tid >> 5, l = tid & 31;
    const int row0 = blockIdx.y * 128, col0 = blockIdx.x * 128;

    float acc[4][4][4] = {};
    gemm_core(g_AO + row0 * EMBED, g_woh + col0 * EMBED, sbase, tid, acc);

    const int wm = (w >> 2) * 64, wn = (w & 3) * 32;
#pragma unroll
    for (int mt = 0; mt < 4; mt++) {
        int r = row0 + wm + mt * 16 + (l >> 2);
#pragma unroll
        for (int nt = 0; nt < 4; nt++) {
            int cc = col0 + wn + nt * 8 + 2 * (l & 3);
            float b0 = bo[cc], b1 = bo[cc + 1];
            *(float2*)(out + r * EMBED + cc) =
                make_float2(acc[mt][nt][0] + b0, acc[mt][nt][1] + b1);
            *(float2*)(out + (r + 8) * EMBED + cc) =
                make_float2(acc[mt][nt][2] + b0, acc[mt][nt][3] + b1);
        }
    }
}

// ======================= flash attention, fp16 mma ==========================
// CTA per (qtile128, head, batch). 8 warps, warp = 16 q rows.
// S-GEMM uses fp16 accumulators: sv comes out packed as half2 in exactly the
// PV A-fragment layout. Softmax = hmax2 / hsub2 / ex2.f16x2 (no conversions).
// PV + li (ones-column) keep fp32 accumulators.
#define A_RS    144                   // bytes per row (72 halfs)
#define A_QP    18432                 // 128 * 144
#define A_KV    9216                  // K stage: 64 * 144
#define A_VST   10368                 // V stage: 72 * 144 (64 kv + ones/zero)
#define A_OFF_K A_QP
#define A_OFF_V (A_QP + 3 * A_KV)
#define A_SMEM  (A_QP + 3 * A_KV + 3 * A_VST)   // 77184

__device__ __forceinline__ void load_kv(const __half* __restrict__ Kg,
                                        const __half* __restrict__ Vg,
                                        uint32_t kbuf, uint32_t vbuf,
                                        int kv0, int tid) {
#pragma unroll
    for (int t = 0; t < 2; t++) {
        int c = tid + t * 256;
        int r = c >> 3, ch = c & 7;
        cp_async16(kbuf + (uint32_t)(r * A_RS + ch * 16),
                   Kg + (kv0 + r) * HDIM + ch * 8);
    }
#pragma unroll
    for (int t = 0; t < 2; t++) {
        int c = tid + t * 256;
        int r = c >> 3, ch = c & 7;   // r = d row of V^T (0..63)
        cp_async16(vbuf + (uint32_t)(r * A_RS + ch * 16),
                   Vg + r * SEQ + kv0 + ch * 8);
    }
}

__global__ void __launch_bounds__(256, 2) attn_tc()
{
    extern __shared__ char dyn[];
    uint32_t sb = smem_u32(dyn);
    const int tid = threadIdx.x, w = tid >> 5, l = tid & 31;
    const int qb = blockIdx.x, h = blockIdx.y, nb = blockIdx.z;

    const __half* Qg = g_Q + ((nb * HEADS + h) * SEQ + qb * 128) * HDIM;
    const __half* Kg = g_K + (nb * HEADS + h) * SEQ * HDIM;
    const __half* Vg = g_V + (nb * HEADS + h) * HDIM * SEQ;   // [D][L]

    uint32_t sQ = sb, sK = sb + A_OFF_K, sV = sb + A_OFF_V;

    // Q tile FIRST (oldest cp.async group)
#pragma unroll
    for (int t = 0; t < 4; t++) {
        int c = tid + t * 256;
        int r = c >> 3, ch = c & 7;
        cp_async16(sQ + (uint32_t)(r * A_RS + ch * 16),
                   Qg + r * HDIM + ch * 8);
    }
    CP_COMMIT();
    load_kv(Kg, Vg, sK, sV, 0, tid);  CP_COMMIT();
    load_kv(Kg, Vg, sK + A_KV, sV + A_VST, 64, tid);  CP_COMMIT();

    // init ones/zero rows (64..71) of all 3 V stages
    {
        __half* smh = (__half*)dyn;
        for (int idx = tid; idx < 3 * 8 * 72; idx += 256) {
            int st = idx / (8 * 72);
            int rr = (idx / 72) & 7;
            int cc = idx % 72;
            smh[(A_OFF_V + st * A_VST + (64 + rr) * A_RS) / 2 + cc] =
                (rr == 0) ? __float2half_rn(1.0f) : __float2half_rn(0.0f);
        }
    }

    const int wm = w * 16;
    const uint32_t arow = (uint32_t)(l & 15);
    const uint32_t acol = (uint32_t)((l >> 4) * 16);
    const uint32_t brow = (uint32_t)(((l >> 4) & 1) * 8 + (l & 7));
    const uint32_t bcol = (uint32_t)(((l >> 3) & 1) * 16);
    const uint32_t orow = (uint32_t)(64 + (l & 7));            // ones rows
    const uint32_t ocol = (uint32_t)(((l >> 3) & 1) * 16);

    // hoist Q fragments (loop-invariant); also publishes ones-rows
    CP_WAIT2();          // Q group retired
    __syncthreads();     // Q + ones visible CTA-wide
    uint32_t qf[4][4];
#pragma unroll
    for (int ks = 0; ks < 4; ks++)
        ldm_x4(qf[ks], sQ + (wm + arow) * A_RS + acol + (uint32_t)(ks * 32));

    float o[8][4] = {};
    float o5[4] = {};                 // li accumulator (ones column)
    float mi0 = -1e30f, mi1 = -1e30f;
    const uint32_t NEGINF2 = 0xFC00FC00u;   // half2(-inf,-inf)

    const int NIT = SEQ / 64;
    for (int it = 0; it < NIT; it++) {
        CP_WAIT1();
        __syncthreads();
        if (it + 2 < NIT) {
            load_kv(Kg, Vg, sK + (uint32_t)((it + 2) % 3) * A_KV,
                    sV + (uint32_t)((it + 2) % 3) * A_VST, (it + 2) * 64, tid);
        }
        CP_COMMIT();
        uint32_t kb = sK + (uint32_t)(it % 3) * A_KV;
        uint32_t vb = sV + (uint32_t)(it % 3) * A_VST;

        // ---- S = Q @ K^T, fp16 accumulate (packed half2 outputs) ----
        uint32_t svl[8], svh[8];      // lo = row g, hi = row g+8
#pragma unroll
        for (int nt = 0; nt < 8; nt++) { svl[nt] = 0u; svh[nt] = 0u; }
#pragma unroll
        for (int ks = 0; ks < 4; ks++) {
            uint32_t kk2 = (uint32_t)(ks * 32);
#pragma unroll
            for (int bp = 0; bp < 4; bp++) {
                uint32_t b[4];
                ldm_x4(b, kb + (bp * 16 + brow) * A_RS + bcol + kk2);
                mma_f16h(svl[bp * 2 + 0], svh[bp * 2 + 0], qf[ks], b[0], b[1]);
                mma_f16h(svl[bp * 2 + 1], svh[bp * 2 + 1], qf[ks], b[2], b[3]);
            }
        }

        // ---- row max (half2 tree) + rescale ----
        uint32_t m2l = NEGINF2, m2h = NEGINF2;
#pragma unroll
        for (int nt = 0; nt < 8; nt++) {
            m2l = hmax2u(m2l, svl[nt]);
            m2h = hmax2u(m2h, svh[nt]);
        }
        float rm0 = h2max_f(m2l), rm1 = h2max_f(m2h);
#pragma unroll
        for (int off = 1; off <= 2; off <<= 1) {
            rm0 = fmaxf(rm0, __shfl_xor_sync(0xffffffffu, rm0, off));
            rm1 = fmaxf(rm1, __shfl_xor_sync(0xffffffffu, rm1, off));
        }
        float mn0 = fmaxf(mi0, rm0), mn1 = fmaxf(mi1, rm1);
        float c0 = fexp2(mi0 - mn0), c1 = fexp2(mi1 - mn1);
        mi0 = mn0;  mi1 = mn1;
#pragma unroll
        for (int dt = 0; dt < 8; dt++) {
            o[dt][0] *= c0; o[dt][1] *= c0; o[dt][2] *= c1; o[dt][3] *= c1;
        }
        o5[0] *= c0; o5[1] *= c0; o5[2] *= c1; o5[3] *= c1;

        __half2 mn0h2 = __float2half2_rn(mn0);
        __half2 mn1h2 = __float2half2_rn(mn1);
        uint32_t mn0u = *(uint32_t*)&mn0h2, mn1u = *(uint32_t*)&mn1h2;

        // ---- per k-slice: exp2 (f16x2) -> P frags -> PV + li mma ----
#pragma unroll
        for (int ks = 0; ks < 4; ks++) {
            uint32_t pa[4];
            pa[0] = hexp2(hsub2u(svl[2*ks],   mn0u));
            pa[1] = hexp2(hsub2u(svh[2*ks],   mn1u));
            pa[2] = hexp2(hsub2u(svl[2*ks+1], mn0u));
            pa[3] = hexp2(hsub2u(svh[2*ks+1], mn1u));
            uint32_t kk2 = (uint32_t)(ks * 32);
            // li: P @ ones-column (row 64 of V^T tile)
            uint32_t ob[2];
            ldm_x2(ob, vb + orow * A_RS + ocol + kk2);
            mma_f16(o5, pa, ob[0], ob[1]);
#pragma unroll
            for (int bp = 0; bp < 4; bp++) {
                uint32_t b[4];
                ldm_x4(b, vb + (bp * 16 + brow) * A_RS + bcol + kk2);
                mma_f16(o[bp * 2 + 0], pa, b[0], b[1]);
                mma_f16(o[bp * 2 + 1], pa, b[2], b[3]);
            }
        }
    }

    // li lives in lanes with (l&3)==0: o5[0] = li(row g), o5[2] = li(row g+8)
    float li0 = __shfl_sync(0xffffffffu, o5[0], l & ~3);
    float li1 = __shfl_sync(0xffffffffu, o5[2], l & ~3);

    // epilogue -> g_AO fp16 [N,L,E]
    float inv0 = 1.f / li0, inv1 = 1.f / li1;
    int r0 = qb * 128 + wm + (l >> 2);
    __half* Og = g_AO + (nb * SEQ + r0) * EMBED + h * HDIM;
#pragma unroll
    for (int dt = 0; dt < 8; dt++) {
        int cc = dt * 8 + 2 * (l & 3);
        __half2 v0 = __floats2half2_rn(o[dt][0] * inv0, o[dt][1] * inv0);
        __half2 v1 = __floats2half2_rn(o[dt][2] * inv1, o[dt][3] * inv1);
        *(__half2*)(Og + cc) = v0;
        *(__half2*)(Og + 8 * EMBED + cc) = v1;
    }
}

// ============================================================================
extern "C" void kernel_launch(void* const* d_in, const int* in_sizes, int n_in,
                              void* d_out, int out_size)
{
    const float* x  = (const float*)d_in[0];
    const float* Wq = (const float*)d_in[1];
    const float* Wk = (const float*)d_in[2];
    const float* Wv = (const float*)d_in[3];
    const float* Wo = (const float*)d_in[4];
    const float* bo = (const float*)d_in[5];
    float* out = (float*)d_out;

    cudaFuncSetAttribute(qkv_tc,  cudaFuncAttributeMaxDynamicSharedMemorySize, G_SMEM);
    cudaFuncSetAttribute(proj_tc, cudaFuncAttributeMaxDynamicSharedMemorySize, G_SMEM);
    cudaFuncSetAttribute(attn_tc, cudaFuncAttributeMaxDynamicSharedMemorySize, A_SMEM);
    cudaFuncSetAttribute(qkv_tc,  cudaFuncAttributePreferredSharedMemoryCarveout,
                         cudaSharedmemCarveoutMaxShared);
    cudaFuncSetAttribute(proj_tc, cudaFuncAttributePreferredSharedMemoryCarveout,
                         cudaSharedmemCarveoutMaxShared);
    cudaFuncSetAttribute(attn_tc, cudaFuncAttributePreferredSharedMemoryCarveout,
                         cudaSharedmemCarveoutMaxShared);

    dim3 gp(512, 5);
    prep_cvt<<<gp, 256>>>(x, Wq, Wk, Wv, Wo);

    dim3 g1(EMBED / 128, MTOT / 128, 3);
    qkv_tc<<<g1, 256, G_SMEM>>>();

    dim3 g2(SEQ / 128, HEADS, NBATCH);
    attn_tc<<<g2, 256, A_SMEM>>>();

    dim3 g3(EMBED / 128, MTOT / 128);
    proj_tc<<<g3, 256, G_SMEM>>>(bo, out);
}

// round 14
// speedup vs baseline: 1.0749x; 1.0244x over previous
#include <cuda_runtime.h>
#include <cuda_fp16.h>
#include <cstdint>

#define EMBED 1024
#define HEADS 16
#define HDIM  64
#define NBATCH 2
#define SEQ   2048
#define MTOT  (NBATCH * SEQ)   // 4096

// ---------------- scratch (device globals: allocation-free) ----------------
__device__ __align__(16) __half g_Q[NBATCH * HEADS * SEQ * HDIM];  // [N,H,L,D] prescaled log2e/32
__device__ __align__(16) __half g_K[NBATCH * HEADS * SEQ * HDIM];  // [N,H,L,D]
__device__ __align__(16) __half g_V[NBATCH * HEADS * SEQ * HDIM];  // [N,H,D,L] transposed
__device__ __align__(16) __half g_AO[MTOT * EMBED];                // [N,L,E]
__device__ __align__(16) __half g_xh[MTOT * EMBED];
__device__ __align__(16) __half g_wqh[EMBED * EMBED];
__device__ __align__(16) __half g_wkh[EMBED * EMBED];
__device__ __align__(16) __half g_wvh[EMBED * EMBED];
__device__ __align__(16) __half g_woh[EMBED * EMBED];

// ======================= helpers (arch-neutral PTX) =========================
__device__ __forceinline__ float fexp2(float x) {
    float y;
    asm("ex2.approx.ftz.f32 %0, %1;" : "=f"(y) : "f"(x));
    return y;
}
__device__ __forceinline__ uint32_t smem_u32(const void* p) {
    uint32_t a;
    asm("{ .reg .u64 t; cvta.to.shared.u64 t, %1; cvt.u32.u64 %0, t; }"
        : "=r"(a) : "l"(p));
    return a;
}
__device__ __forceinline__ void cp_async16(uint32_t s, const void* g) {
    asm volatile("cp.async.cg.shared.global [%0], [%1], 16;" :: "r"(s), "l"(g));
}
#define CP_COMMIT() asm volatile("cp.async.commit_group;" ::: "memory")
#define CP_WAIT1()  asm volatile("cp.async.wait_group 1;" ::: "memory")
#define CP_WAIT2()  asm volatile("cp.async.wait_group 2;" ::: "memory")

__device__ __forceinline__ void ldm_x4(uint32_t (&r)[4], uint32_t a) {
    asm volatile("ldmatrix.sync.aligned.m8n8.x4.shared.b16 {%0,%1,%2,%3}, [%4];"
                 : "=r"(r[0]), "=r"(r[1]), "=r"(r[2]), "=r"(r[3]) : "r"(a));
}
__device__ __forceinline__ void ldm_x2(uint32_t (&r)[2], uint32_t a) {
    asm volatile("ldmatrix.sync.aligned.m8n8.x2.shared.b16 {%0,%1}, [%2];"
                 : "=r"(r[0]), "=r"(r[1]) : "r"(a));
}
// fp16 mma m16n8k16, fp32 accumulate
__device__ __forceinline__ void mma_f16(float (&d)[4], const uint32_t (&a)[4],
                                        uint32_t b0, uint32_t b1) {
    asm volatile("mma.sync.aligned.m16n8k16.row.col.f32.f16.f16.f32 "
                 "{%0,%1,%2,%3}, {%4,%5,%6,%7}, {%8,%9}, {%0,%1,%2,%3};"
                 : "+f"(d[0]), "+f"(d[1]), "+f"(d[2]), "+f"(d[3])
                 : "r"(a[0]), "r"(a[1]), "r"(a[2]), "r"(a[3]),
                   "r"(b0), "r"(b1));
}
// fp16 mma m16n8k16, fp16 accumulate
__device__ __forceinline__ void mma_f16h(uint32_t& d0, uint32_t& d1,
                                         const uint32_t (&a)[4],
                                         uint32_t b0, uint32_t b1) {
    asm volatile("mma.sync.aligned.m16n8k16.row.col.f16.f16.f16.f16 "
                 "{%0,%1}, {%2,%3,%4,%5}, {%6,%7}, {%0,%1};"
                 : "+r"(d0), "+r"(d1)
                 : "r"(a[0]), "r"(a[1]), "r"(a[2]), "r"(a[3]),
                   "r"(b0), "r"(b1));
}
__device__ __forceinline__ uint32_t hexp2(uint32_t d) {
    uint32_t r;
    asm("ex2.approx.f16x2 %0, %1;" : "=r"(r) : "r"(d));
    return r;
}
__device__ __forceinline__ uint32_t hmax2u(uint32_t a, uint32_t b) {
    __half2 r = __hmax2(*(__half2*)&a, *(__half2*)&b);
    return *(uint32_t*)&r;
}
__device__ __forceinline__ uint32_t hsub2u(uint32_t a, uint32_t b) {
    __half2 r = __hsub2(*(__half2*)&a, *(__half2*)&b);
    return *(uint32_t*)&r;
}
__device__ __forceinline__ float h2max_f(uint32_t a) {
    __half2 h = *(__half2*)&a;
    return fmaxf(__half2float(__low2half(h)), __half2float(__high2half(h)));
}

// ======================= prep: convert fp32 -> fp16 =========================
__global__ void __launch_bounds__(256) prep_cvt(
    const float* __restrict__ x,  const float* __restrict__ wq,
    const float* __restrict__ wk, const float* __restrict__ wv,
    const float* __restrict__ wo)
{
    int t = blockIdx.y;
    const float* src = (t == 0) ? x : (t == 1) ? wq : (t == 2) ? wk
                     : (t == 3) ? wv : wo;
    __half* dst = (t == 0) ? g_xh : (t == 1) ? g_wqh : (t == 2) ? g_wkh
                : (t == 3) ? g_wvh : g_woh;
    int n4 = ((t == 0) ? MTOT * EMBED : EMBED * EMBED) / 4;
    for (int i = blockIdx.x * blockDim.x + threadIdx.x; i < n4;
         i += gridDim.x * blockDim.x) {
        float4 v = ((const float4*)src)[i];
        __half2 h0 = __floats2half2_rn(v.x, v.y);
        __half2 h1 = __floats2half2_rn(v.z, v.w);
        ((uint2*)dst)[i] = make_uint2(*(uint32_t*)&h0, *(uint32_t*)&h1);
    }
}

// ======================= fp16 mma GEMM core (128x128xK) =====================
// 4 warps (128 threads), warp tile 64x64: 8 LDSM -> 32 mma per k16 slice.
// BK=64 halfs (128B/row, padded to 144B). 3-stage cp.async, 1 sync/iter.
#define G_RS     144
#define G_TILEB  18432                // 128 * 144
#define GSTAGE   36864
#define G_SMEM   110592               // 3 stages

__device__ __forceinline__ void g_load_tile(const __half* __restrict__ g,
                                            uint32_t s, int k0, int tid) {
#pragma unroll
    for (int t = 0; t < 8; t++) {
        int c = tid + t * 128;        // 0..1023 16B chunks
        int row = c >> 3, ch = c & 7;
        cp_async16(s + (uint32_t)(row * G_RS + ch * 16),
                   g + row * EMBED + k0 + ch * 8);
    }
}

__device__ __forceinline__ void gemm_core(const __half* __restrict__ Ag,
                                          const __half* __restrict__ Bg,
                                          uint32_t sbase, int tid,
                                          float acc[4][8][4]) {
    const int w = tid >> 5, l = tid & 31;
    const int wm = (w >> 1) * 64, wn = (w & 1) * 64;
    const uint32_t arow = (uint32_t)(l & 15);
    const uint32_t acol = (uint32_t)((l >> 4) * 16);
    const uint32_t brow = (uint32_t)(((l >> 4) & 1) * 8 + (l & 7));
    const uint32_t bcol = (uint32_t)(((l >> 3) & 1) * 16);

    uint32_t sA = sbase, sB = sbase + G_TILEB;
    g_load_tile(Ag, sA, 0, tid);  g_load_tile(Bg, sB, 0, tid);  CP_COMMIT();
    g_load_tile(Ag, sA + GSTAGE, 64, tid);
    g_load_tile(Bg, sB + GSTAGE, 64, tid);  CP_COMMIT();

    const int NIT = EMBED / 64;       // 16
    for (int i = 0; i < NIT; i++) {
        CP_WAIT1();
        __syncthreads();
        if (i + 2 < NIT) {
            uint32_t po = (uint32_t)((i + 2) % 3) * GSTAGE;
            g_load_tile(Ag, sA + po, (i + 2) * 64, tid);
            g_load_tile(Bg, sB + po, (i + 2) * 64, tid);
        }
        CP_COMMIT();
        uint32_t bo = (uint32_t)(i % 3) * GSTAGE;
        uint32_t ab = sA + bo, bb = sB + bo;
#pragma unroll
        for (int ks = 0; ks < 4; ks++) {       // four k16 slices per BK=64
            uint32_t kk2 = (uint32_t)(ks * 32);
            uint32_t a[4][4];
#pragma unroll
            for (int mt = 0; mt < 4; mt++)
                ldm_x4(a[mt], ab + (wm + mt * 16 + arow) * G_RS + acol + kk2);
#pragma unroll
            for (int bp = 0; bp < 4; bp++) {
                uint32_t b[4];
                ldm_x4(b, bb + (wn + bp * 16 + brow) * G_RS + bcol + kk2);
#pragma unroll
                for (int mt = 0; mt < 4; mt++) {
                    mma_f16(acc[mt][bp * 2 + 0], a[mt], b[0], b[1]);
                    mma_f16(acc[mt][bp * 2 + 1], a[mt], b[2], b[3]);
                }
            }
        }
    }
}

// ---------------------------- QKV -------------------------------------------
__global__ void __launch_bounds__(128, 2) qkv_tc()
{
    extern __shared__ char dyn[];
    uint32_t sbase = smem_u32(dyn);
    const int tid = threadIdx.x, w = tid >> 5, l = tid & 31;
    const int row0 = blockIdx.y * 128, col0 = blockIdx.x * 128;
    const __half* W = (blockIdx.z == 0) ? g_wqh : (blockIdx.z == 1) ? g_wkh : g_wvh;

    float acc[4][8][4] = {};
    gemm_core(g_xh + row0 * EMBED, W + col0 * EMBED, sbase, tid, acc);

    const int wm = (w >> 1) * 64, wn = (w & 1) * 64;
    const int nb = row0 >> 11;
    const float qscale = 1.4426950408889634f / 32.0f;   // log2(e)/sqrt(E)

    if (blockIdx.z < 2) {
        __half* dst = (blockIdx.z == 0) ? g_Q : g_K;
        float sc = (blockIdx.z == 0) ? qscale : 1.0f;
#pragma unroll
        for (int mt = 0; mt < 4; mt++) {
            int r  = row0 + wm + mt * 16 + (l >> 2);
            int ll = r & (SEQ - 1);
#pragma unroll
            for (int nt = 0; nt < 8; nt++) {
                int cc = col0 + wn + nt * 8 + 2 * (l & 3);
                int h = cc >> 6, d = cc & 63;
                __half* p = dst + ((nb * HEADS + h) * SEQ + ll) * HDIM + d;
                __half2 v0 = __floats2half2_rn(acc[mt][nt][0] * sc, acc[mt][nt][1] * sc);
                __half2 v1 = __floats2half2_rn(acc[mt][nt][2] * sc, acc[mt][nt][3] * sc);
                *(__half2*)p = v0;
                *(__half2*)(p + 8 * HDIM) = v1;
            }
        }
    } else {
        // V: transpose via smem -> g_V [N,H,D,L] fp16
        __half* ts = (__half*)dyn;            // [128 cc][136]
        __syncthreads();
#pragma unroll
        for (int mt = 0; mt < 4; mt++) {
            int r = wm + mt * 16 + (l >> 2);
#pragma unroll
            for (int nt = 0; nt < 8; nt++) {
                int cc = wn + nt * 8 + 2 * (l & 3);
                ts[cc * 136 + r]           = __float2half_rn(acc[mt][nt][0]);
                ts[(cc + 1) * 136 + r]     = __float2half_rn(acc[mt][nt][1]);
                ts[cc * 136 + r + 8]       = __float2half_rn(acc[mt][nt][2]);
                ts[(cc + 1) * 136 + r + 8] = __float2half_rn(acc[mt][nt][3]);
            }
        }
        __syncthreads();
        int l0base = row0 & (SEQ - 1);
#pragma unroll
        for (int q = 0; q < 16; q++) {
            int e  = q * 128 + tid;           // 0..2047
            int cc = e >> 4;                  // 0..127
            int ls = e & 15;
            uint4 v = *(const uint4*)&ts[cc * 136 + ls * 8];
            int gc = col0 + cc;
            int h = gc >> 6, d = gc & 63;
            *(uint4*)(g_V + ((nb * HEADS + h) * HDIM + d) * SEQ + l0base + ls * 8) = v;
        }
    }
}

// ---------------------------- proj ------------------------------------------
__global__ void __launch_bounds__(128, 2) proj_tc(
    const float* __restrict__ bo, float* __restrict__ out)
{
    extern __shared__ char dyn[];
    uint32_t sbase = smem_u32(dyn);
    const int tid = threadIdx.x, w = tid >> 5, l = tid & 31;
    const int row0 = blockIdx.y * 128, col0 = blockIdx.x * 128;

    float acc[4][8][4] = {};
    gemm_core(g_AO + row0 * EMBED, g_woh + col0 * EMBED, sbase, tid, acc);

    const int wm = (w >> 1) * 64, wn = (w & 1) * 64;
#pragma unroll
    for (int mt = 0; mt < 4; mt++) {
        int r = row0 + wm + mt * 16 + (l >> 2);
#pragma unroll
        for (int nt = 0; nt < 8; nt++) {
            int cc = col0 + wn + nt * 8 + 2 * (l & 3);
            float b0 = bo[cc], b1 = bo[cc + 1];
            *(float2*)(out + r * EMBED + cc) =
                make_float2(acc[mt][nt][0] + b0, acc[mt][nt][1] + b1);
            *(float2*)(out + (r + 8) * EMBED + cc) =
                make_float2(acc[mt][nt][2] + b0, acc[mt][nt][3] + b1);
        }
    }
}

// ======================= flash attention, fp16 mma ==========================
// (unchanged from R13: fp16-acc S, register-resident P, tensor-core li)
#define A_RS    144
#define A_QP    18432
#define A_KV    9216
#define A_VST   10368
#define A_OFF_K A_QP
#define A_OFF_V (A_QP + 3 * A_KV)
#define A_SMEM  (A_QP + 3 * A_KV + 3 * A_VST)   // 77184

__device__ __forceinline__ void load_kv(const __half* __restrict__ Kg,
                                        const __half* __restrict__ Vg,
                                        uint32_t kbuf, uint32_t vbuf,
                                        int kv0, int tid) {
#pragma unroll
    for (int t = 0; t < 2; t++) {
        int c = tid + t * 256;
        int r = c >> 3, ch = c & 7;
        cp_async16(kbuf + (uint32_t)(r * A_RS + ch * 16),
                   Kg + (kv0 + r) * HDIM + ch * 8);
    }
#pragma unroll
    for (int t = 0; t < 2; t++) {
        int c = tid + t * 256;
        int r = c >> 3, ch = c & 7;
        cp_async16(vbuf + (uint32_t)(r * A_RS + ch * 16),
                   Vg + r * SEQ + kv0 + ch * 8);
    }
}

__global__ void __launch_bounds__(256, 2) attn_tc()
{
    extern __shared__ char dyn[];
    uint32_t sb = smem_u32(dyn);
    const int tid = threadIdx.x, w = tid >> 5, l = tid & 31;
    const int qb = blockIdx.x, h = blockIdx.y, nb = blockIdx.z;

    const __half* Qg = g_Q + ((nb * HEADS + h) * SEQ + qb * 128) * HDIM;
    const __half* Kg = g_K + (nb * HEADS + h) * SEQ * HDIM;
    const __half* Vg = g_V + (nb * HEADS + h) * HDIM * SEQ;

    uint32_t sQ = sb, sK = sb + A_OFF_K, sV = sb + A_OFF_V;

#pragma unroll
    for (int t = 0; t < 4; t++) {
        int c = tid + t * 256;
        int r = c >> 3, ch = c & 7;
        cp_async16(sQ + (uint32_t)(r * A_RS + ch * 16),
                   Qg + r * HDIM + ch * 8);
    }
    CP_COMMIT();
    load_kv(Kg, Vg, sK, sV, 0, tid);  CP_COMMIT();
    load_kv(Kg, Vg, sK + A_KV, sV + A_VST, 64, tid);  CP_COMMIT();

    {
        __half* smh = (__half*)dyn;
        for (int idx = tid; idx < 3 * 8 * 72; idx += 256) {
            int st = idx / (8 * 72);
            int rr = (idx / 72) & 7;
            int cc = idx % 72;
            smh[(A_OFF_V + st * A_VST + (64 + rr) * A_RS) / 2 + cc] =
                (rr == 0) ? __float2half_rn(1.0f) : __float2half_rn(0.0f);
        }
    }

    const int wm = w * 16;
    const uint32_t arow = (uint32_t)(l & 15);
    const uint32_t acol = (uint32_t)((l >> 4) * 16);
    const uint32_t brow = (uint32_t)(((l >> 4) & 1) * 8 + (l & 7));
    const uint32_t bcol = (uint32_t)(((l >> 3) & 1) * 16);
    const uint32_t orow = (uint32_t)(64 + (l & 7));
    const uint32_t ocol = (uint32_t)(((l >> 3) & 1) * 16);

    CP_WAIT2();
    __syncthreads();
    uint32_t qf[4][4];
#pragma unroll
    for (int ks = 0; ks < 4; ks++)
        ldm_x4(qf[ks], sQ + (wm + arow) * A_RS + acol + (uint32_t)(ks * 32));

    float o[8][4] = {};
    float o5[4] = {};
    float mi0 = -1e30f, mi1 = -1e30f;
    const uint32_t NEGINF2 = 0xFC00FC00u;

    const int NIT = SEQ / 64;
    for (int it = 0; it < NIT; it++) {
        CP_WAIT1();
        __syncthreads();
        if (it + 2 < NIT) {
            load_kv(Kg, Vg, sK + (uint32_t)((it + 2) % 3) * A_KV,
                    sV + (uint32_t)((it + 2) % 3) * A_VST, (it + 2) * 64, tid);
        }
        CP_COMMIT();
        uint32_t kb = sK + (uint32_t)(it % 3) * A_KV;
        uint32_t vb = sV + (uint32_t)(it % 3) * A_VST;

        uint32_t svl[8], svh[8];
#pragma unroll
        for (int nt = 0; nt < 8; nt++) { svl[nt] = 0u; svh[nt] = 0u; }
#pragma unroll
        for (int ks = 0; ks < 4; ks++) {
            uint32_t kk2 = (uint32_t)(ks * 32);
#pragma unroll
            for (int bp = 0; bp < 4; bp++) {
                uint32_t b[4];
                ldm_x4(b, kb + (bp * 16 + brow) * A_RS + bcol + kk2);
                mma_f16h(svl[bp * 2 + 0], svh[bp * 2 + 0], qf[ks], b[0], b[1]);
                mma_f16h(svl[bp * 2 + 1], svh[bp * 2 + 1], qf[ks], b[2], b[3]);
            }
        }

        uint32_t m2l = NEGINF2, m2h = NEGINF2;
#pragma unroll
        for (int nt = 0; nt < 8; nt++) {
            m2l = hmax2u(m2l, svl[nt]);
            m2h = hmax2u(m2h, svh[nt]);
        }
        float rm0 = h2max_f(m2l), rm1 = h2max_f(m2h);
#pragma unroll
        for (int off = 1; off <= 2; off <<= 1) {
            rm0 = fmaxf(rm0, __shfl_xor_sync(0xffffffffu, rm0, off));
            rm1 = fmaxf(rm1, __shfl_xor_sync(0xffffffffu, rm1, off));
        }
        float mn0 = fmaxf(mi0, rm0), mn1 = fmaxf(mi1, rm1);
        float c0 = fexp2(mi0 - mn0), c1 = fexp2(mi1 - mn1);
        mi0 = mn0;  mi1 = mn1;
#pragma unroll
        for (int dt = 0; dt < 8; dt++) {
            o[dt][0] *= c0; o[dt][1] *= c0; o[dt][2] *= c1; o[dt][3] *= c1;
        }
        o5[0] *= c0; o5[1] *= c0; o5[2] *= c1; o5[3] *= c1;

        __half2 mn0h2 = __float2half2_rn(mn0);
        __half2 mn1h2 = __float2half2_rn(mn1);
        uint32_t mn0u = *(uint32_t*)&mn0h2, mn1u = *(uint32_t*)&mn1h2;

#pragma unroll
        for (int ks = 0; ks < 4; ks++) {
            uint32_t pa[4];
            pa[0] = hexp2(hsub2u(svl[2*ks],   mn0u));
            pa[1] = hexp2(hsub2u(svh[2*ks],   mn1u));
            pa[2] = hexp2(hsub2u(svl[2*ks+1], mn0u));
            pa[3] = hexp2(hsub2u(svh[2*ks+1], mn1u));
            uint32_t kk2 = (uint32_t)(ks * 32);
            uint32_t ob[2];
            ldm_x2(ob, vb + orow * A_RS + ocol + kk2);
            mma_f16(o5, pa, ob[0], ob[1]);
#pragma unroll
            for (int bp = 0; bp < 4; bp++) {
                uint32_t b[4];
                ldm_x4(b, vb + (bp * 16 + brow) * A_RS + bcol + kk2);
                mma_f16(o[bp * 2 + 0], pa, b[0], b[1]);
                mma_f16(o[bp * 2 + 1], pa, b[2], b[3]);
            }
        }
    }

    float li0 = __shfl_sync(0xffffffffu, o5[0], l & ~3);
    float li1 = __shfl_sync(0xffffffffu, o5[2], l & ~3);

    float inv0 = 1.f / li0, inv1 = 1.f / li1;
    int r0 = qb * 128 + wm + (l >> 2);
    __half* Og = g_AO + (nb * SEQ + r0) * EMBED + h * HDIM;
#pragma unroll
    for (int dt = 0; dt < 8; dt++) {
        int cc = dt * 8 + 2 * (l & 3);
        __half2 v0 = __floats2half2_rn(o[dt][0] * inv0, o[dt][1] * inv0);
        __half2 v1 = __floats2half2_rn(o[dt][2] * inv1, o[dt][3] * inv1);
        *(__half2*)(Og + cc) = v0;
        *(__half2*)(Og + 8 * EMBED + cc) = v1;
    }
}

// ============================================================================
extern "C" void kernel_launch(void* const* d_in, const int* in_sizes, int n_in,
                              void* d_out, int out_size)
{
    const float* x  = (const float*)d_in[0];
    const float* Wq = (const float*)d_in[1];
    const float* Wk = (const float*)d_in[2];
    const float* Wv = (const float*)d_in[3];
    const float* Wo = (const float*)d_in[4];
    const float* bo = (const float*)d_in[5];
    float* out = (float*)d_out;

    cudaFuncSetAttribute(qkv_tc,  cudaFuncAttributeMaxDynamicSharedMemorySize, G_SMEM);
    cudaFuncSetAttribute(proj_tc, cudaFuncAttributeMaxDynamicSharedMemorySize, G_SMEM);
    cudaFuncSetAttribute(attn_tc, cudaFuncAttributeMaxDynamicSharedMemorySize, A_SMEM);
    cudaFuncSetAttribute(qkv_tc,  cudaFuncAttributePreferredSharedMemoryCarveout,
                         cudaSharedmemCarveoutMaxShared);
    cudaFuncSetAttribute(proj_tc, cudaFuncAttributePreferredSharedMemoryCarveout,
                         cudaSharedmemCarveoutMaxShared);
    cudaFuncSetAttribute(attn_tc, cudaFuncAttributePreferredSharedMemoryCarveout,
                         cudaSharedmemCarveoutMaxShared);

    dim3 gp(512, 5);
    prep_cvt<<<gp, 256>>>(x, Wq, Wk, Wv, Wo);

    dim3 g1(EMBED / 128, MTOT / 128, 3);
    qkv_tc<<<g1, 128, G_SMEM>>>();

    dim3 g2(SEQ / 128, HEADS, NBATCH);
    attn_tc<<<g2, 256, A_SMEM>>>();

    dim3 g3(EMBED / 128, MTOT / 128);
    proj_tc<<<g3, 128, G_SMEM>>>(bo, out);
}

// round 15
// speedup vs baseline: 1.0970x; 1.0205x over previous
#include <cuda_runtime.h>
#include <cuda_fp16.h>
#include <cstdint>

#define EMBED 1024
#define HEADS 16
#define HDIM  64
#define NBATCH 2
#define SEQ   2048
#define MTOT  (NBATCH * SEQ)   // 4096

// ---------------- scratch (device globals: allocation-free) ----------------
__device__ __align__(16) __half g_Q[NBATCH * HEADS * SEQ * HDIM];  // [N,H,L,D] prescaled log2e/32
__device__ __align__(16) __half g_K[NBATCH * HEADS * SEQ * HDIM];  // [N,H,L,D]
__device__ __align__(16) __half g_V[NBATCH * HEADS * SEQ * HDIM];  // [N,H,D,L] transposed
__device__ __align__(16) __half g_AO[MTOT * EMBED];                // [N,L,E]
__device__ __align__(16) __half g_xh[MTOT * EMBED];
__device__ __align__(16) __half g_wqh[EMBED * EMBED];
__device__ __align__(16) __half g_wkh[EMBED * EMBED];
__device__ __align__(16) __half g_wvh[EMBED * EMBED];
__device__ __align__(16) __half g_woh[EMBED * EMBED];

// ======================= helpers (arch-neutral PTX) =========================
__device__ __forceinline__ float fexp2(float x) {
    float y;
    asm("ex2.approx.ftz.f32 %0, %1;" : "=f"(y) : "f"(x));
    return y;
}
__device__ __forceinline__ uint32_t smem_u32(const void* p) {
    uint32_t a;
    asm("{ .reg .u64 t; cvta.to.shared.u64 t, %1; cvt.u32.u64 %0, t; }"
        : "=r"(a) : "l"(p));
    return a;
}
__device__ __forceinline__ void cp_async16(uint32_t s, const void* g) {
    asm volatile("cp.async.cg.shared.global [%0], [%1], 16;" :: "r"(s), "l"(g));
}
#define CP_COMMIT() asm volatile("cp.async.commit_group;" ::: "memory")
#define CP_WAIT1()  asm volatile("cp.async.wait_group 1;" ::: "memory")
#define CP_WAIT2()  asm volatile("cp.async.wait_group 2;" ::: "memory")

__device__ __forceinline__ void ldm_x4(uint32_t (&r)[4], uint32_t a) {
    asm volatile("ldmatrix.sync.aligned.m8n8.x4.shared.b16 {%0,%1,%2,%3}, [%4];"
                 : "=r"(r[0]), "=r"(r[1]), "=r"(r[2]), "=r"(r[3]) : "r"(a));
}
__device__ __forceinline__ void ldm_x2(uint32_t (&r)[2], uint32_t a) {
    asm volatile("ldmatrix.sync.aligned.m8n8.x2.shared.b16 {%0,%1}, [%2];"
                 : "=r"(r[0]), "=r"(r[1]) : "r"(a));
}
// fp16 mma m16n8k16, fp32 accumulate
__device__ __forceinline__ void mma_f16(float (&d)[4], const uint32_t (&a)[4],
                                        uint32_t b0, uint32_t b1) {
    asm volatile("mma.sync.aligned.m16n8k16.row.col.f32.f16.f16.f32 "
                 "{%0,%1,%2,%3}, {%4,%5,%6,%7}, {%8,%9}, {%0,%1,%2,%3};"
                 : "+f"(d[0]), "+f"(d[1]), "+f"(d[2]), "+f"(d[3])
                 : "r"(a[0]), "r"(a[1]), "r"(a[2]), "r"(a[3]),
                   "r"(b0), "r"(b1));
}
// fp16 mma m16n8k16, fp16 accumulate
__device__ __forceinline__ void mma_f16h(uint32_t& d0, uint32_t& d1,
                                         const uint32_t (&a)[4],
                                         uint32_t b0, uint32_t b1) {
    asm volatile("mma.sync.aligned.m16n8k16.row.col.f16.f16.f16.f16 "
                 "{%0,%1}, {%2,%3,%4,%5}, {%6,%7}, {%0,%1};"
                 : "+r"(d0), "+r"(d1)
                 : "r"(a[0]), "r"(a[1]), "r"(a[2]), "r"(a[3]),
                   "r"(b0), "r"(b1));
}
__device__ __forceinline__ uint32_t hexp2(uint32_t d) {
    uint32_t r;
    asm("ex2.approx.f16x2 %0, %1;" : "=r"(r) : "r"(d));
    return r;
}
__device__ __forceinline__ uint32_t hmax2u(uint32_t a, uint32_t b) {
    __half2 r = __hmax2(*(__half2*)&a, *(__half2*)&b);
    return *(uint32_t*)&r;
}
__device__ __forceinline__ uint32_t hsub2u(uint32_t a, uint32_t b) {
    __half2 r = __hsub2(*(__half2*)&a, *(__half2*)&b);
    return *(uint32_t*)&r;
}
__device__ __forceinline__ float h2max_f(uint32_t a) {
    __half2 h = *(__half2*)&a;
    return fmaxf(__half2float(__low2half(h)), __half2float(__high2half(h)));
}

// ======================= prep: convert fp32 -> fp16 =========================
__global__ void __launch_bounds__(256) prep_cvt(
    const float* __restrict__ x,  const float* __restrict__ wq,
    const float* __restrict__ wk, const float* __restrict__ wv,
    const float* __restrict__ wo)
{
    int t = blockIdx.y;
    const float* src = (t == 0) ? x : (t == 1) ? wq : (t == 2) ? wk
                     : (t == 3) ? wv : wo;
    __half* dst = (t == 0) ? g_xh : (t == 1) ? g_wqh : (t == 2) ? g_wkh
                : (t == 3) ? g_wvh : g_woh;
    int n4 = ((t == 0) ? MTOT * EMBED : EMBED * EMBED) / 4;
    for (int i = blockIdx.x * blockDim.x + threadIdx.x; i < n4;
         i += gridDim.x * blockDim.x) {
        float4 v = ((const float4*)src)[i];
        __half2 h0 = __floats2half2_rn(v.x, v.y);
        __half2 h1 = __floats2half2_rn(v.z, v.w);
        ((uint2*)dst)[i] = make_uint2(*(uint32_t*)&h0, *(uint32_t*)&h1);
    }
}

// ======================= fp16 mma GEMM core (128x128xK) =====================
// 4 warps (128 threads), warp tile 64x64. BK=64, 3-stage cp.async.
#define G_RS     144
#define G_TILEB  18432                // 128 * 144
#define GSTAGE   36864
#define G_SMEM   110592               // 3 stages

__device__ __forceinline__ void g_load_tile(const __half* __restrict__ g,
                                            uint32_t s, int k0, int tid) {
#pragma unroll
    for (int t = 0; t < 8; t++) {
        int c = tid + t * 128;        // 0..1023 16B chunks
        int row = c >> 3, ch = c & 7;
        cp_async16(s + (uint32_t)(row * G_RS + ch * 16),
                   g + row * EMBED + k0 + ch * 8);
    }
}

__device__ __forceinline__ void gemm_core(const __half* __restrict__ Ag,
                                          const __half* __restrict__ Bg,
                                          uint32_t sbase, int tid,
                                          float acc[4][8][4]) {
    const int w = tid >> 5, l = tid & 31;
    const int wm = (w >> 1) * 64, wn = (w & 1) * 64;
    const uint32_t arow = (uint32_t)(l & 15);
    const uint32_t acol = (uint32_t)((l >> 4) * 16);
    const uint32_t brow = (uint32_t)(((l >> 4) & 1) * 8 + (l & 7));
    const uint32_t bcol = (uint32_t)(((l >> 3) & 1) * 16);

    uint32_t sA = sbase, sB = sbase + G_TILEB;
    g_load_tile(Ag, sA, 0, tid);  g_load_tile(Bg, sB, 0, tid);  CP_COMMIT();
    g_load_tile(Ag, sA + GSTAGE, 64, tid);
    g_load_tile(Bg, sB + GSTAGE, 64, tid);  CP_COMMIT();

    const int NIT = EMBED / 64;       // 16
    for (int i = 0; i < NIT; i++) {
        CP_WAIT1();
        __syncthreads();
        if (i + 2 < NIT) {
            uint32_t po = (uint32_t)((i + 2) % 3) * GSTAGE;
            g_load_tile(Ag, sA + po, (i + 2) * 64, tid);
            g_load_tile(Bg, sB + po, (i + 2) * 64, tid);
        }
        CP_COMMIT();
        uint32_t bo = (uint32_t)(i % 3) * GSTAGE;
        uint32_t ab = sA + bo, bb = sB + bo;
#pragma unroll
        for (int ks = 0; ks < 4; ks++) {       // four k16 slices per BK=64
            uint32_t kk2 = (uint32_t)(ks * 32);
            uint32_t a[4][4];
#pragma unroll
            for (int mt = 0; mt < 4; mt++)
                ldm_x4(a[mt], ab + (wm + mt * 16 + arow) * G_RS + acol + kk2);
#pragma unroll
            for (int bp = 0; bp < 4; bp++) {
                uint32_t b[4];
                ldm_x4(b, bb + (wn + bp * 16 + brow) * G_RS + bcol + kk2);
#pragma unroll
                for (int mt = 0; mt < 4; mt++) {
                    mma_f16(acc[mt][bp * 2 + 0], a[mt], b[0], b[1]);
                    mma_f16(acc[mt][bp * 2 + 1], a[mt], b[2], b[3]);
                }
            }
        }
    }
}

// ---------------------------- QKV -------------------------------------------
__global__ void __launch_bounds__(128, 2) qkv_tc()
{
    extern __shared__ char dyn[];
    uint32_t sbase = smem_u32(dyn);
    const int tid = threadIdx.x, w = tid >> 5, l = tid & 31;
    const int row0 = blockIdx.y * 128, col0 = blockIdx.x * 128;
    const __half* W = (blockIdx.z == 0) ? g_wqh : (blockIdx.z == 1) ? g_wkh : g_wvh;

    float acc[4][8][4] = {};
    gemm_core(g_xh + row0 * EMBED, W + col0 * EMBED, sbase, tid, acc);

    const int wm = (w >> 1) * 64, wn = (w & 1) * 64;
    const int nb = row0 >> 11;
    const float qscale = 1.4426950408889634f / 32.0f;   // log2(e)/sqrt(E)

    if (blockIdx.z < 2) {
        __half* dst = (blockIdx.z == 0) ? g_Q : g_K;
        float sc = (blockIdx.z == 0) ? qscale : 1.0f;
#pragma unroll
        for (int mt = 0; mt < 4; mt++) {
            int r  = row0 + wm + mt * 16 + (l >> 2);
            int ll = r & (SEQ - 1);
#pragma unroll
            for (int nt = 0; nt < 8; nt++) {
                int cc = col0 + wn + nt * 8 + 2 * (l & 3);
                int h = cc >> 6, d = cc & 63;
                __half* p = dst + ((nb * HEADS + h) * SEQ + ll) * HDIM + d;
                __half2 v0 = __floats2half2_rn(acc[mt][nt][0] * sc, acc[mt][nt][1] * sc);
                __half2 v1 = __floats2half2_rn(acc[mt][nt][2] * sc, acc[mt][nt][3] * sc);
                *(__half2*)p = v0;
                *(__half2*)(p + 8 * HDIM) = v1;
            }
        }
    } else {
        // V: transpose via smem -> g_V [N,H,D,L] fp16
        __half* ts = (__half*)dyn;            // [128 cc][136]
        __syncthreads();
#pragma unroll
        for (int mt = 0; mt < 4; mt++) {
            int r = wm + mt * 16 + (l >> 2);
#pragma unroll
            for (int nt = 0; nt < 8; nt++) {
                int cc = wn + nt * 8 + 2 * (l & 3);
                ts[cc * 136 + r]           = __float2half_rn(acc[mt][nt][0]);
                ts[(cc + 1) * 136 + r]     = __float2half_rn(acc[mt][nt][1]);
                ts[cc * 136 + r + 8]       = __float2half_rn(acc[mt][nt][2]);
                ts[(cc + 1) * 136 + r + 8] = __float2half_rn(acc[mt][nt][3]);
            }
        }
        __syncthreads();
        int l0base = row0 & (SEQ - 1);
#pragma unroll
        for (int q = 0; q < 16; q++) {
            int e  = q * 128 + tid;           // 0..2047
            int cc = e >> 4;                  // 0..127
            int ls = e & 15;
            uint4 v = *(const uint4*)&ts[cc * 136 + ls * 8];
            int gc = col0 + cc;
            int h = gc >> 6, d = gc & 63;
            *(uint4*)(g_V + ((nb * HEADS + h) * HDIM + d) * SEQ + l0base + ls * 8) = v;
        }
    }
}

// ---------------------------- proj ------------------------------------------
__global__ void __launch_bounds__(128, 2) proj_tc(
    const float* __restrict__ bo, float* __restrict__ out)
{
    extern __shared__ char dyn[];
    uint32_t sbase = smem_u32(dyn);
    const int tid = threadIdx.x, w = tid >> 5, l = tid & 31;
    const int row0 = blockIdx.y * 128, col0 = blockIdx.x * 128;

    float acc[4][8][4] = {};
    gemm_core(g_AO + row0 * EMBED, g_woh + col0 * EMBED, sbase, tid, acc);

    const int wm = (w >> 1) * 64, wn = (w & 1) * 64;
#pragma unroll
    for (int mt = 0; mt < 4; mt++) {
        int r = row0 + wm + mt * 16 + (l >> 2);
#pragma unroll
        for (int nt = 0; nt < 8; nt++) {
            int cc = col0 + wn + nt * 8 + 2 * (l & 3);
            float b0 = bo[cc], b1 = bo[cc + 1];
            *(float2*)(out + r * EMBED + cc) =
                make_float2(acc[mt][nt][0] + b0, acc[mt][nt][1] + b1);
            *(float2*)(out + (r + 8) * EMBED + cc) =
                make_float2(acc[mt][nt][2] + b0, acc[mt][nt][3] + b1);
        }
    }
}

// ======================= flash attention, fp16 mma ==========================
// CTA per (qtile64, head, batch): 4 warps, warp = 16 q rows — per-warp stream
// identical to the 128-row version (no cross-warp fragment sharing), but
// smem 68KB -> 3 CTAs/SM = 12 warps, and 1024 CTAs -> smoother waves.
#define A_RS    144
#define A_QP    9216                  // 64 * 144
#define A_KV    9216
#define A_VST   10368                 // 72 * 144 (64 kv + ones/zero rows)
#define A_OFF_K A_QP
#define A_OFF_V (A_QP + 3 * A_KV)
#define A_SMEM  (A_QP + 3 * A_KV + 3 * A_VST)   // 67968

__device__ __forceinline__ void load_kv(const __half* __restrict__ Kg,
                                        const __half* __restrict__ Vg,
                                        uint32_t kbuf, uint32_t vbuf,
                                        int kv0, int tid) {
#pragma unroll
    for (int t = 0; t < 4; t++) {
        int c = tid + t * 128;
        int r = c >> 3, ch = c & 7;
        cp_async16(kbuf + (uint32_t)(r * A_RS + ch * 16),
                   Kg + (kv0 + r) * HDIM + ch * 8);
    }
#pragma unroll
    for (int t = 0; t < 4; t++) {
        int c = tid + t * 128;
        int r = c >> 3, ch = c & 7;
        cp_async16(vbuf + (uint32_t)(r * A_RS + ch * 16),
                   Vg + r * SEQ + kv0 + ch * 8);
    }
}

__global__ void __launch_bounds__(128, 3) attn_tc()
{
    extern __shared__ char dyn[];
    uint32_t sb = smem_u32(dyn);
    const int tid = threadIdx.x, w = tid >> 5, l = tid & 31;
    const int qb = blockIdx.x, h = blockIdx.y, nb = blockIdx.z;

    const __half* Qg = g_Q + ((nb * HEADS + h) * SEQ + qb * 64) * HDIM;
    const __half* Kg = g_K + (nb * HEADS + h) * SEQ * HDIM;
    const __half* Vg = g_V + (nb * HEADS + h) * HDIM * SEQ;

    uint32_t sQ = sb, sK = sb + A_OFF_K, sV = sb + A_OFF_V;

    // Q tile FIRST (oldest cp.async group): 64 rows x 64 halfs
#pragma unroll
    for (int t = 0; t < 4; t++) {
        int c = tid + t * 128;
        int r = c >> 3, ch = c & 7;
        cp_async16(sQ + (uint32_t)(r * A_RS + ch * 16),
                   Qg + r * HDIM + ch * 8);
    }
    CP_COMMIT();
    load_kv(Kg, Vg, sK, sV, 0, tid);  CP_COMMIT();
    load_kv(Kg, Vg, sK + A_KV, sV + A_VST, 64, tid);  CP_COMMIT();

    // init ones/zero rows (64..71) of all 3 V stages
    {
        __half* smh = (__half*)dyn;
        for (int idx = tid; idx < 3 * 8 * 72; idx += 128) {
            int st = idx / (8 * 72);
            int rr = (idx / 72) & 7;
            int cc = idx % 72;
            smh[(A_OFF_V + st * A_VST + (64 + rr) * A_RS) / 2 + cc] =
                (rr == 0) ? __float2half_rn(1.0f) : __float2half_rn(0.0f);
        }
    }

    const int wm = w * 16;
    const uint32_t arow = (uint32_t)(l & 15);
    const uint32_t acol = (uint32_t)((l >> 4) * 16);
    const uint32_t brow = (uint32_t)(((l >> 4) & 1) * 8 + (l & 7));
    const uint32_t bcol = (uint32_t)(((l >> 3) & 1) * 16);
    const uint32_t orow = (uint32_t)(64 + (l & 7));
    const uint32_t ocol = (uint32_t)(((l >> 3) & 1) * 16);

    CP_WAIT2();
    __syncthreads();
    uint32_t qf[4][4];
#pragma unroll
    for (int ks = 0; ks < 4; ks++)
        ldm_x4(qf[ks], sQ + (wm + arow) * A_RS + acol + (uint32_t)(ks * 32));

    float o[8][4] = {};
    float o5[4] = {};
    float mi0 = -1e30f, mi1 = -1e30f;
    const uint32_t NEGINF2 = 0xFC00FC00u;

    const int NIT = SEQ / 64;
    for (int it = 0; it < NIT; it++) {
        CP_WAIT1();
        __syncthreads();
        if (it + 2 < NIT) {
            load_kv(Kg, Vg, sK + (uint32_t)((it + 2) % 3) * A_KV,
                    sV + (uint32_t)((it + 2) % 3) * A_VST, (it + 2) * 64, tid);
        }
        CP_COMMIT();
        uint32_t kb = sK + (uint32_t)(it % 3) * A_KV;
        uint32_t vb = sV + (uint32_t)(it % 3) * A_VST;

        // ---- S = Q @ K^T, fp16 accumulate ----
        uint32_t svl[8], svh[8];
#pragma unroll
        for (int nt = 0; nt < 8; nt++) { svl[nt] = 0u; svh[nt] = 0u; }
#pragma unroll
        for (int ks = 0; ks < 4; ks++) {
            uint32_t kk2 = (uint32_t)(ks * 32);
#pragma unroll
            for (int bp = 0; bp < 4; bp++) {
                uint32_t b[4];
                ldm_x4(b, kb + (bp * 16 + brow) * A_RS + bcol + kk2);
                mma_f16h(svl[bp * 2 + 0], svh[bp * 2 + 0], qf[ks], b[0], b[1]);
                mma_f16h(svl[bp * 2 + 1], svh[bp * 2 + 1], qf[ks], b[2], b[3]);
            }
        }

        // ---- row max (half2 tree) + rescale ----
        uint32_t m2l = NEGINF2, m2h = NEGINF2;
#pragma unroll
        for (int nt = 0; nt < 8; nt++) {
            m2l = hmax2u(m2l, svl[nt]);
            m2h = hmax2u(m2h, svh[nt]);
        }
        float rm0 = h2max_f(m2l), rm1 = h2max_f(m2h);
#pragma unroll
        for (int off = 1; off <= 2; off <<= 1) {
            rm0 = fmaxf(rm0, __shfl_xor_sync(0xffffffffu, rm0, off));
            rm1 = fmaxf(rm1, __shfl_xor_sync(0xffffffffu, rm1, off));
        }
        float mn0 = fmaxf(mi0, rm0), mn1 = fmaxf(mi1, rm1);
        float c0 = fexp2(mi0 - mn0), c1 = fexp2(mi1 - mn1);
        mi0 = mn0;  mi1 = mn1;
#pragma unroll
        for (int dt = 0; dt < 8; dt++) {
            o[dt][0] *= c0; o[dt][1] *= c0; o[dt][2] *= c1; o[dt][3] *= c1;
        }
        o5[0] *= c0; o5[1] *= c0; o5[2] *= c1; o5[3] *= c1;

        __half2 mn0h2 = __float2half2_rn(mn0);
        __half2 mn1h2 = __float2half2_rn(mn1);
        uint32_t mn0u = *(uint32_t*)&mn0h2, mn1u = *(uint32_t*)&mn1h2;

        // ---- per k-slice: exp2 (f16x2) -> P frags -> PV + li mma ----
#pragma unroll
        for (int ks = 0; ks < 4; ks++) {
            uint32_t pa[4];
            pa[0] = hexp2(hsub2u(svl[2*ks],   mn0u));
            pa[1] = hexp2(hsub2u(svh[2*ks],   mn1u));
            pa[2] = hexp2(hsub2u(svl[2*ks+1], mn0u));
            pa[3] = hexp2(hsub2u(svh[2*ks+1], mn1u));
            uint32_t kk2 = (uint32_t)(ks * 32);
            uint32_t ob[2];
            ldm_x2(ob, vb + orow * A_RS + ocol + kk2);
            mma_f16(o5, pa, ob[0], ob[1]);
#pragma unroll
            for (int bp = 0; bp < 4; bp++) {
                uint32_t b[4];
                ldm_x4(b, vb + (bp * 16 + brow) * A_RS + bcol + kk2);
                mma_f16(o[bp * 2 + 0], pa, b[0], b[1]);
                mma_f16(o[bp * 2 + 1], pa, b[2], b[3]);
            }
        }
    }

    float li0 = __shfl_sync(0xffffffffu, o5[0], l & ~3);
    float li1 = __shfl_sync(0xffffffffu, o5[2], l & ~3);

    // epilogue -> g_AO fp16 [N,L,E]
    float inv0 = 1.f / li0, inv1 = 1.f / li1;
    int r0 = qb * 64 + wm + (l >> 2);
    __half* Og = g_AO + (nb * SEQ + r0) * EMBED + h * HDIM;
#pragma unroll
    for (int dt = 0; dt < 8; dt++) {
        int cc = dt * 8 + 2 * (l & 3);
        __half2 v0 = __floats2half2_rn(o[dt][0] * inv0, o[dt][1] * inv0);
        __half2 v1 = __floats2half2_rn(o[dt][2] * inv1, o[dt][3] * inv1);
        *(__half2*)(Og + cc) = v0;
        *(__half2*)(Og + 8 * EMBED + cc) = v1;
    }
}

// ============================================================================
extern "C" void kernel_launch(void* const* d_in, const int* in_sizes, int n_in,
                              void* d_out, int out_size)
{
    const float* x  = (const float*)d_in[0];
    const float* Wq = (const float*)d_in[1];
    const float* Wk = (const float*)d_in[2];
    const float* Wv = (const float*)d_in[3];
    const float* Wo = (const float*)d_in[4];
    const float* bo = (const float*)d_in[5];
    float* out = (float*)d_out;

    cudaFuncSetAttribute(qkv_tc,  cudaFuncAttributeMaxDynamicSharedMemorySize, G_SMEM);
    cudaFuncSetAttribute(proj_tc, cudaFuncAttributeMaxDynamicSharedMemorySize, G_SMEM);
    cudaFuncSetAttribute(attn_tc, cudaFuncAttributeMaxDynamicSharedMemorySize, A_SMEM);
    cudaFuncSetAttribute(qkv_tc,  cudaFuncAttributePreferredSharedMemoryCarveout,
                         cudaSharedmemCarveoutMaxShared);
    cudaFuncSetAttribute(proj_tc, cudaFuncAttributePreferredSharedMemoryCarveout,
                         cudaSharedmemCarveoutMaxShared);
    cudaFuncSetAttribute(attn_tc, cudaFuncAttributePreferredSharedMemoryCarveout,
                         cudaSharedmemCarveoutMaxShared);

    dim3 gp(512, 5);
    prep_cvt<<<gp, 256>>>(x, Wq, Wk, Wv, Wo);

    dim3 g1(EMBED / 128, MTOT / 128, 3);
    qkv_tc<<<g1, 128, G_SMEM>>>();

    dim3 g2(SEQ / 64, HEADS, NBATCH);
    attn_tc<<<g2, 128, A_SMEM>>>();

    dim3 g3(EMBED / 128, MTOT / 128);
    proj_tc<<<g3, 128, G_SMEM>>>(bo, out);
}